// round 3
// baseline (speedup 1.0000x reference)
#include <cuda_runtime.h>
#include <cuda_bf16.h>
#include <math.h>

#define BB 32
#define TT 256
#define AA 22
#define FIN 16
#define NH 4
#define CC 128
#define HC 512
#define HID 256
#define G4 1024
#define NF (BB*TT)        // 8192 frames
#define LSTM_BLOCKS 128

// ---------------- device scratch (static allocations only) ----------------
__device__ float g_pooled[NF*CC];          // 4 MB
__device__ float g_xg[NF*G4];              // 32 MB (reused for layer0 and layer1 pre-GEMM)
__device__ float g_h0seq[BB*TT*HID];       // 8 MB  [b][t][k]
__device__ float g_hbuf[2*BB*HID];         // double-buffered h
__device__ float g_hlast[BB*HID];
__device__ unsigned g_bar_count;
__device__ volatile unsigned g_bar_sense;

// dtype-robust seq_length read: reference claims int64 but JAX x64-off yields
// int32. Lengths are in [T/2, T] (>=128, never 0), so for little-endian int64
// the odd 32-bit words are all zero; for int32 they are >=128.
__device__ __forceinline__ int read_len(const int* p, int b)
{
    bool is64 = (p[1] == 0) && (p[3] == 0);
    return is64 ? p[2*b] : p[b];
}

// ---------------- fused GAT (both layers + pool), one block per frame -----
#define OFF_XS     0          // 22*16 = 352
#define OFF_H1     352        // 22*512 = 11264 (reused as x1 after relu)
#define OFF_ASRC   11616      // 88
#define OFF_ADST   11704      // 88
#define OFF_ALPHA1 11792      // 22*22*4 = 1936
#define OFF_H2     13728      // 22*128 = 2816
#define OFF_A2S    16544      // 22
#define OFF_A2D    16566      // 22
#define OFF_ALPHA2 16588      // 484
#define GAT_SMEM_FLOATS 17072
#define GAT_SMEM_BYTES (GAT_SMEM_FLOATS*4)

extern "C" __global__ void __launch_bounds__(256)
gat_kernel(const float* __restrict__ feat,
           const float* __restrict__ W1, const float* __restrict__ aS1,
           const float* __restrict__ aD1, const float* __restrict__ b1,
           const float* __restrict__ W2, const float* __restrict__ aS2,
           const float* __restrict__ aD2, const float* __restrict__ b2,
           float* __restrict__ pooled)
{
    extern __shared__ float sm[];
    float* xs     = sm + OFF_XS;
    float* h1     = sm + OFF_H1;    // later x1
    float* asrc   = sm + OFF_ASRC;
    float* adst   = sm + OFF_ADST;
    float* alpha1 = sm + OFF_ALPHA1;
    float* h2     = sm + OFF_H2;
    float* a2s    = sm + OFF_A2S;
    float* a2d    = sm + OFF_A2D;
    float* alpha2 = sm + OFF_ALPHA2;

    const int n   = blockIdx.x;
    const int tid = threadIdx.x;

    // load frame x [22][16]
    const float* xg = feat + (long)n * (AA*FIN);
    for (int i = tid; i < AA*FIN; i += 256) xs[i] = xg[i];
    __syncthreads();

    // h1[a][hc] = sum_f x[a][f] * W1[f][hc]
    #pragma unroll
    for (int s = 0; s < 44; s++) {
        int o = tid + s*256;
        int a = o >> 9, hc = o & 511;
        float acc = 0.f;
        #pragma unroll
        for (int f = 0; f < FIN; f++) acc += xs[a*FIN+f] * W1[f*HC+hc];
        h1[o] = acc;
    }
    __syncthreads();

    // attention scores a_src/a_dst: 22*4 each
    if (tid < 176) {
        int p = tid; bool dst = (p >= 88); if (dst) p -= 88;
        int a = p >> 2, hd = p & 3;
        const float* att = dst ? aD1 : aS1;
        float acc = 0.f;
        for (int c = 0; c < CC; c++) acc += h1[a*HC + hd*CC + c] * att[hd*CC + c];
        (dst ? adst : asrc)[a*4 + hd] = acc;
    }
    __syncthreads();

    // softmax over sources j for each (i, head)
    if (tid < 88) {
        int i = tid >> 2, hd = tid & 3;
        float di = adst[i*4 + hd];
        float e[AA]; float m = -1e30f;
        #pragma unroll
        for (int j = 0; j < AA; j++) {
            float v = di + asrc[j*4 + hd];
            v = (v > 0.f) ? v : 0.2f*v;
            e[j] = v; m = fmaxf(m, v);
        }
        float ssum = 0.f;
        #pragma unroll
        for (int j = 0; j < AA; j++) { float ex = __expf(e[j]-m); e[j] = ex; ssum += ex; }
        float inv = 1.f/ssum;
        #pragma unroll
        for (int j = 0; j < AA; j++) alpha1[(i*AA+j)*4 + hd] = e[j]*inv;
    }
    __syncthreads();

    // out1 = alpha1 @ h1   (into registers)
    float o1[44];
    #pragma unroll
    for (int s = 0; s < 44; s++) {
        int o = tid + s*256;
        int a = o >> 9, hc = o & 511, hd = hc >> 7;
        float acc = 0.f;
        #pragma unroll
        for (int j = 0; j < AA; j++)
            acc += alpha1[(a*AA+j)*4 + hd] * h1[j*HC + hc];
        o1[s] = acc;
    }
    __syncthreads();
    // write x1 = relu(out1 + b1) back into h1 storage; zero h2
    #pragma unroll
    for (int s = 0; s < 44; s++) {
        int o = tid + s*256;
        h1[o] = fmaxf(o1[s] + b1[o & 511], 0.f);
    }
    for (int i = tid; i < AA*CC; i += 256) h2[i] = 0.f;
    __syncthreads();

    // h2 = x1 @ W2  : 256 threads = 2 k-halves x 128 columns, smem atomics reduce
    {
        int c = tid & 127, half = tid >> 7;
        float acc[AA];
        #pragma unroll
        for (int i = 0; i < AA; i++) acc[i] = 0.f;
        int k0 = half * 256;
        for (int k = k0; k < k0 + 256; k++) {
            float w = W2[k*CC + c];
            #pragma unroll
            for (int i = 0; i < AA; i++) acc[i] += h1[i*HC + k] * w;
        }
        #pragma unroll
        for (int i = 0; i < AA; i++) atomicAdd(&h2[i*CC + c], acc[i]);
    }
    __syncthreads();

    // layer-2 attention scores
    if (tid < 44) {
        int i = tid % AA; bool dst = (tid >= AA);
        const float* att = dst ? aD2 : aS2;
        float acc = 0.f;
        for (int c = 0; c < CC; c++) acc += h2[i*CC + c] * att[c];
        (dst ? a2d : a2s)[i] = acc;
    }
    __syncthreads();
    if (tid < AA) {
        int i = tid;
        float di = a2d[i];
        float e[AA]; float m = -1e30f;
        #pragma unroll
        for (int j = 0; j < AA; j++) {
            float v = di + a2s[j];
            v = (v > 0.f) ? v : 0.2f*v;
            e[j] = v; m = fmaxf(m, v);
        }
        float ssum = 0.f;
        #pragma unroll
        for (int j = 0; j < AA; j++) { float ex = __expf(e[j]-m); e[j] = ex; ssum += ex; }
        float inv = 1.f/ssum;
        #pragma unroll
        for (int j = 0; j < AA; j++) alpha2[i*AA+j] = e[j]*inv;
    }
    __syncthreads();

    // pooled[c] = mean_i relu(b2[c] + sum_j alpha2[i][j]*h2[j][c])
    if (tid < CC) {
        int c = tid;
        float bc = b2[c];
        float s = 0.f;
        #pragma unroll
        for (int i = 0; i < AA; i++) {
            float acc = bc;
            #pragma unroll
            for (int j = 0; j < AA; j++) acc += alpha2[i*AA+j] * h2[j*CC + c];
            s += fmaxf(acc, 0.f);
        }
        pooled[(long)n*CC + c] = s * (1.f/22.f);
    }
}

// ---------------- input GEMM: out[n][j] = X[n]·W[j] + bi[j] + bh[j] --------
extern "C" __global__ void __launch_bounds__(256)
gemm_xg(const float* __restrict__ X, const float* __restrict__ W,
        const float* __restrict__ bi, const float* __restrict__ bh,
        float* __restrict__ out, int K)
{
    __shared__ float xsm[16*256];
    const int n0 = blockIdx.x * 16;
    const int tid = threadIdx.x;
    for (int idx = tid; idx < 16*K; idx += 256) xsm[idx] = X[(long)n0*K + idx];
    __syncthreads();

    float acc[16][4];
    #pragma unroll
    for (int nn = 0; nn < 16; nn++)
        #pragma unroll
        for (int m = 0; m < 4; m++) acc[nn][m] = 0.f;

    const int r0 = tid, r1 = tid+256, r2 = tid+512, r3 = tid+768;
    for (int k = 0; k < K; k += 4) {
        float4 w0 = *(const float4*)&W[(long)r0*K + k];
        float4 w1 = *(const float4*)&W[(long)r1*K + k];
        float4 w2 = *(const float4*)&W[(long)r2*K + k];
        float4 w3 = *(const float4*)&W[(long)r3*K + k];
        #pragma unroll
        for (int nn = 0; nn < 16; nn++) {
            float4 xv = *(const float4*)&xsm[nn*K + k];
            acc[nn][0] += xv.x*w0.x + xv.y*w0.y + xv.z*w0.z + xv.w*w0.w;
            acc[nn][1] += xv.x*w1.x + xv.y*w1.y + xv.z*w1.z + xv.w*w1.w;
            acc[nn][2] += xv.x*w2.x + xv.y*w2.y + xv.z*w2.z + xv.w*w2.w;
            acc[nn][3] += xv.x*w3.x + xv.y*w3.y + xv.z*w3.z + xv.w*w3.w;
        }
    }
    float bsum0 = bi[r0]+bh[r0], bsum1 = bi[r1]+bh[r1], bsum2 = bi[r2]+bh[r2], bsum3 = bi[r3]+bh[r3];
    #pragma unroll
    for (int nn = 0; nn < 16; nn++) {
        long base = (long)(n0+nn)*G4;
        out[base + r0] = acc[nn][0] + bsum0;
        out[base + r1] = acc[nn][1] + bsum1;
        out[base + r2] = acc[nn][2] + bsum2;
        out[base + r3] = acc[nn][3] + bsum3;
    }
}

// ---------------- persistent LSTM recurrence with grid barrier -------------
__device__ __forceinline__ void grid_barrier(unsigned* sense, int nblocks)
{
    __threadfence();               // release all threads' prior global writes
    __syncthreads();
    if (threadIdx.x == 0) {
        unsigned s = *sense ^ 1u; *sense = s;
        unsigned prev = atomicAdd(&g_bar_count, 1u);
        if (prev == (unsigned)(nblocks - 1)) {
            g_bar_count = 0u;
            __threadfence();
            g_bar_sense = s;
        } else {
            while (g_bar_sense != s) { }
        }
        __threadfence();
    }
    __syncthreads();
}

__device__ __forceinline__ float sigmoidf_(float x) { return 1.f/(1.f + expf(-x)); }

// 128 blocks, each owns 2 hidden units (8 gate rows) for all 32 batches.
extern "C" __global__ void __launch_bounds__(256)
lstm_kernel(const float* __restrict__ xg, const float* __restrict__ Whh,
            const int* __restrict__ slen,
            float* __restrict__ hbuf, float* __restrict__ outseq,
            float* __restrict__ hlast, int writeSeq)
{
    __shared__ float hs[BB*HID];     // 32 KB
    __shared__ float ws[8*260];      // padded rows
    __shared__ float gsm[BB*8];

    const int tid = threadIdx.x;
    const int kbase = blockIdx.x * 2;

    // load this block's 8 gate rows of Whh into smem (rows padded to 260)
    for (int idx = tid; idx < 8*HID; idx += 256) {
        int r = idx >> 8, k = idx & 255;
        int j = (r >> 1)*HID + kbase + (r & 1);
        ws[r*260 + k] = Whh[(long)j*HID + k];
    }

    const int b = tid >> 3, r = tid & 7;
    const int myj = (r >> 1)*HID + kbase + (r & 1);
    const int kk  = kbase + (r & 1);
    const int mylen = read_len(slen, b);
    float creg = 0.f;
    unsigned sense = 0u;
    __syncthreads();

    for (int t = 0; t < TT; t++) {
        const float* hprev = hbuf + (t & 1)*BB*HID;
        float* hnext       = hbuf + ((t+1) & 1)*BB*HID;

        // stage full h into smem
        for (int idx = tid*4; idx < BB*HID; idx += 1024)
            *(float4*)&hs[idx] = *(const float4*)&hprev[idx];
        __syncthreads();

        // g[b][myj] = xg + h·Whh_row
        float acc = 0.f;
        #pragma unroll 8
        for (int k = 0; k < HID; k += 4) {
            float4 h4 = *(const float4*)&hs[b*HID + k];
            float4 w4 = *(const float4*)&ws[r*260 + k];
            acc += h4.x*w4.x + h4.y*w4.y + h4.z*w4.z + h4.w*w4.w;
        }
        acc += xg[(long)(b*TT + t)*G4 + myj];
        gsm[b*8 + r] = acc;
        __syncthreads();

        if (r < 2) {
            float gi = sigmoidf_(gsm[b*8 + 0 + r]);
            float gf = sigmoidf_(gsm[b*8 + 2 + r]);
            float gg = tanhf    (gsm[b*8 + 4 + r]);
            float go = sigmoidf_(gsm[b*8 + 6 + r]);
            float cn = gf*creg + gi*gg;
            float hn = go * tanhf(cn);
            if (t >= mylen) { cn = creg; hn = hs[b*HID + kk]; }
            creg = cn;
            hnext[b*HID + kk] = hn;
            if (writeSeq) outseq[(long)(b*TT + t)*HID + kk] = hn;
            if (hlast && t == TT-1) hlast[b*HID + kk] = hn;
        }
        grid_barrier(&sense, LSTM_BLOCKS);   // 256 barriers total (even -> replay-safe)
    }
}

extern "C" __global__ void zero_kernel(float* p, int nelem)
{
    int i = blockIdx.x*256 + threadIdx.x;
    if (i < nelem) p[i] = 0.f;
}

extern "C" __global__ void final_kernel(const float* __restrict__ hlast,
                                        const float* __restrict__ w,
                                        const float* __restrict__ bias,
                                        float* __restrict__ out)
{
    int b = threadIdx.x;
    if (b < BB) {
        float s = bias[0];
        for (int k = 0; k < HID; k++) s += hlast[b*HID + k] * w[k];
        out[b] = s;
    }
}

// ---------------- launch ----------------
extern "C" void kernel_launch(void* const* d_in, const int* in_sizes, int n_in,
                              void* d_out, int out_size)
{
    const float* feat  = (const float*)d_in[0];
    const int*   slen  = (const int*)d_in[1];
    const float* W1   = (const float*)d_in[2];
    const float* aS1  = (const float*)d_in[3];
    const float* aD1  = (const float*)d_in[4];
    const float* b1   = (const float*)d_in[5];
    const float* W2   = (const float*)d_in[6];
    const float* aS2  = (const float*)d_in[7];
    const float* aD2  = (const float*)d_in[8];
    const float* b2   = (const float*)d_in[9];
    const float* Wih0 = (const float*)d_in[10];
    const float* Whh0 = (const float*)d_in[11];
    const float* bih0 = (const float*)d_in[12];
    const float* bhh0 = (const float*)d_in[13];
    const float* Wih1 = (const float*)d_in[14];
    const float* Whh1 = (const float*)d_in[15];
    const float* bih1 = (const float*)d_in[16];
    const float* bhh1 = (const float*)d_in[17];
    const float* clfw = (const float*)d_in[18];
    const float* clfb = (const float*)d_in[19];
    float* out = (float*)d_out;

    cudaFuncSetAttribute(gat_kernel, cudaFuncAttributeMaxDynamicSharedMemorySize, GAT_SMEM_BYTES);

    float* pooled; cudaGetSymbolAddress((void**)&pooled, g_pooled);
    float* xg;     cudaGetSymbolAddress((void**)&xg,     g_xg);
    float* h0seq;  cudaGetSymbolAddress((void**)&h0seq,  g_h0seq);
    float* hbuf;   cudaGetSymbolAddress((void**)&hbuf,   g_hbuf);
    float* hlast;  cudaGetSymbolAddress((void**)&hlast,  g_hlast);

    // 1) fused GAT + pooling over all 8192 frames
    gat_kernel<<<NF, 256, GAT_SMEM_BYTES>>>(feat, W1, aS1, aD1, b1, W2, aS2, aD2, b2, pooled);

    // 2) layer-0 input transform: xg = pooled @ Wih0^T + bih0 + bhh0
    gemm_xg<<<NF/16, 256>>>(pooled, Wih0, bih0, bhh0, xg, CC);

    // 3) layer-0 recurrence
    zero_kernel<<<(2*BB*HID + 255)/256, 256>>>(hbuf, 2*BB*HID);
    lstm_kernel<<<LSTM_BLOCKS, 256>>>(xg, Whh0, slen, hbuf, h0seq, nullptr, 1);

    // 4) layer-1 input transform: xg = h0seq @ Wih1^T + bih1 + bhh1
    gemm_xg<<<NF/16, 256>>>(h0seq, Wih1, bih1, bhh1, xg, HID);

    // 5) layer-1 recurrence (only final h needed)
    zero_kernel<<<(2*BB*HID + 255)/256, 256>>>(hbuf, 2*BB*HID);
    lstm_kernel<<<LSTM_BLOCKS, 256>>>(xg, Whh1, slen, hbuf, nullptr, hlast, 0);

    // 6) classifier
    final_kernel<<<1, 32>>>(hlast, clfw, clfb, out);
}